// round 16
// baseline (speedup 1.0000x reference)
#include <cuda_runtime.h>
#include <cuda_fp16.h>
#include <cstdint>

#define SEQ 8192
#define CTX 2048
#define DK  128
#define NT  64                    // SEQ/128 s-tiles (stats granularity)
#define SPLIT 16
#define TCH (SEQ / SPLIT)         // 512 t-columns per pv block
#define SCALE 11.313708498984760f
#define THRESH -25.0f

// ---- scratch (device globals) ----
__device__ uint32_t g_xh[(size_t)SEQ * (CTX / 2)];         // 32 MB fp16 x
__device__ uint32_t g_wh[3 * DK * (CTX / 2)];              // 3 MB   [mat][n][k]
__device__ uint32_t g_qh[(size_t)SEQ * (DK / 2)];          // 2 MB fp16 q
__device__ uint32_t g_kh[(size_t)SEQ * (DK / 2)];          // 2 MB fp16 k
__device__ float  g_v[SEQ * DK];                           // 4 MB fp32 v
__device__ __half g_vt[(size_t)DK * SEQ];                  // 2 MB fp16 v^T [dk][t]
__device__ float  g_pm[NT * SEQ];                          // per-tile col max (scaled)
__device__ float  g_pzt[NT * SEQ];                         // per-tile Z partial
__device__ float  g_m[SEQ];
__device__ float  g_rz[SEQ];
__device__ float  g_po[SPLIT][SEQ * DK];                   // 64 MB pv partials

// ============================================================
// helpers
// ============================================================
__device__ __forceinline__ uint32_t smem_u32(const void* p) {
    uint32_t a;
    asm("{ .reg .u64 t; cvta.to.shared.u64 t, %1; cvt.u32.u64 %0, t; }" : "=r"(a) : "l"(p));
    return a;
}
__device__ __forceinline__ void cp16(uint32_t dst, const void* src) {
    asm volatile("cp.async.cg.shared.global [%0], [%1], 16;" :: "r"(dst), "l"(src));
}
#define CP_COMMIT asm volatile("cp.async.commit_group;" ::: "memory")
#define CP_WAIT0  asm volatile("cp.async.wait_group 0;" ::: "memory")

__device__ __forceinline__ uint32_t packh2(float x0, float x1) {
    uint32_t h;
    asm("cvt.rn.f16x2.f32 %0, %1, %2;" : "=r"(h) : "f"(x1), "f"(x0));
    return h;
}
__device__ __forceinline__ void mma16(float* c, const uint32_t* a, const uint32_t* b) {
    asm("mma.sync.aligned.m16n8k16.row.col.f32.f16.f16.f32 "
        "{%0,%1,%2,%3}, {%4,%5,%6,%7}, {%8,%9}, {%0,%1,%2,%3};"
        : "+f"(c[0]), "+f"(c[1]), "+f"(c[2]), "+f"(c[3])
        : "r"(a[0]), "r"(a[1]), "r"(a[2]), "r"(a[3]), "r"(b[0]), "r"(b[1]));
}
__device__ __forceinline__ void ldsm_x4(uint32_t* d, uint32_t a) {
    asm volatile("ldmatrix.sync.aligned.m8n8.x4.shared.b16 {%0,%1,%2,%3}, [%4];"
                 : "=r"(d[0]), "=r"(d[1]), "=r"(d[2]), "=r"(d[3]) : "r"(a));
}
__device__ __forceinline__ void sts32(uint32_t addr, uint32_t v) {
    asm volatile("st.shared.b32 [%0], %1;" :: "r"(addr), "r"(v) : "memory");
}

// ============================================================
// K0a: x -> row-major fp16
// ============================================================
__global__ __launch_bounds__(256) void cvt_x_kernel(const float* __restrict__ x)
{
    const int i = blockIdx.x * 256 + threadIdx.x;
    float4 v = reinterpret_cast<const float4*>(x)[i];
    g_xh[2 * (size_t)i]     = packh2(v.x, v.y);
    g_xh[2 * (size_t)i + 1] = packh2(v.z, v.w);
}

// K0b: w^T -> fp16, [mat][n][k]
__global__ __launch_bounds__(256) void cvt_w_kernel(
    const float* __restrict__ wq, const float* __restrict__ wk, const float* __restrict__ wv)
{
    const int i = blockIdx.x * 256 + threadIdx.x;
    const int mat = i / (DK * 512);
    const int r = i % (DK * 512);
    const int n = r >> 9;
    const int k4 = (r & 511) * 4;
    const float* w = (mat == 0) ? wq : (mat == 1) ? wk : wv;
    float w0 = w[(size_t)(k4 + 0) * DK + n];
    float w1 = w[(size_t)(k4 + 1) * DK + n];
    float w2 = w[(size_t)(k4 + 2) * DK + n];
    float w3 = w[(size_t)(k4 + 3) * DK + n];
    uint32_t* base = g_wh + ((size_t)(mat * DK + n)) * 1024 + (k4 >> 1);
    base[0] = packh2(w0, w1);
    base[1] = packh2(w2, w3);
}

// ============================================================
// K1: Q/K/V = x @ w, 1-pass fp16. Tile 64m x 128n, BK=64, 48KB 2-buf, 4 CTAs/SM.
// ============================================================
__global__ __launch_bounds__(256, 4) void qkv_kernel()
{
    extern __shared__ uint32_t dsm[];
    const uint32_t base0 = smem_u32(dsm);

    const int m0 = blockIdx.x * 64;
    const int mat = blockIdx.y;
    const int tid = threadIdx.x;
    const int wid = tid >> 5, lane = tid & 31;
    const int g = lane >> 2, tg = lane & 3;
    const int wm = (wid & 1) * 32;
    const int wn = (wid >> 1) * 32;
    const int lr = (lane & 7) + ((lane >> 3) & 1) * 8;
    const int lc = lane >> 4;

    float acc[2][4][4];
#pragma unroll
    for (int i = 0; i < 2; i++)
#pragma unroll
        for (int j = 0; j < 4; j++)
#pragma unroll
            for (int q = 0; q < 4; q++) acc[i][j][q] = 0.f;

#define QKV_ISSUE(kc, buf)                                                        \
    do {                                                                          \
        _Pragma("unroll")                                                         \
        for (int j = 0; j < 2; j++) {                                             \
            int idx = tid + j * 256, row = idx >> 3, q = idx & 7;                 \
            cp16(base0 + (buf) * 8192 + row * 128 + ((q ^ (row & 7)) << 4),       \
                 g_xh + (size_t)(m0 + row) * (CTX / 2) + (kc) * 32 + q * 4);      \
        }                                                                         \
        _Pragma("unroll")                                                         \
        for (int j = 0; j < 4; j++) {                                             \
            int idx = tid + j * 256, row = idx >> 3, q = idx & 7;                 \
            cp16(base0 + 16384 + (buf) * 16384 + row * 128 + ((q ^ (row & 7)) << 4), \
                 g_wh + (size_t)(mat * DK + row) * 1024 + (kc) * 32 + q * 4);     \
        }                                                                         \
    } while (0)

    QKV_ISSUE(0, 0);
    CP_COMMIT;
    const int NC = CTX / 64;
    for (int kc = 0; kc < NC; kc++) {
        CP_WAIT0;
        __syncthreads();
        if (kc + 1 < NC) { QKV_ISSUE(kc + 1, (kc + 1) & 1); CP_COMMIT; }
        const int buf = kc & 1;
        const uint32_t aB = base0 + buf * 8192u;
        const uint32_t bB = base0 + 16384u + buf * 16384u;
#pragma unroll
        for (int j = 0; j < 4; j++) {
            uint32_t Aq[2][4], Bq[2][4];
#pragma unroll
            for (int mt = 0; mt < 2; mt++) {
                const int ra = wm + mt * 16 + lr;
                ldsm_x4(Aq[mt], aB + ra * 128 + (((j * 2 + lc) ^ (ra & 7)) << 4));
            }
#pragma unroll
            for (int pr = 0; pr < 2; pr++) {
                const int rb = wn + pr * 16 + lr;
                ldsm_x4(Bq[pr], bB + rb * 128 + (((j * 2 + lc) ^ (rb & 7)) << 4));
            }
#pragma unroll
            for (int nt = 0; nt < 4; nt++) {
                uint32_t bh[2] = {Bq[nt >> 1][nt & 1], Bq[nt >> 1][2 + (nt & 1)]};
#pragma unroll
                for (int mt = 0; mt < 2; mt++) mma16(acc[mt][nt], Aq[mt], bh);
            }
        }
    }
#undef QKV_ISSUE

#pragma unroll
    for (int mt = 0; mt < 2; mt++) {
#pragma unroll
        for (int nt = 0; nt < 4; nt++) {
            const int r0 = m0 + wm + mt * 16 + g;
            const int col = wn + nt * 8 + 2 * tg;
            if (mat == 2) {
                *reinterpret_cast<float2*>(g_v + (size_t)r0 * DK + col) =
                    make_float2(acc[mt][nt][0], acc[mt][nt][1]);
                *reinterpret_cast<float2*>(g_v + (size_t)(r0 + 8) * DK + col) =
                    make_float2(acc[mt][nt][2], acc[mt][nt][3]);
            } else {
                uint32_t* dst = (mat == 0) ? g_qh : g_kh;
                dst[(size_t)r0 * 64 + (col >> 1)] = packh2(acc[mt][nt][0], acc[mt][nt][1]);
                dst[(size_t)(r0 + 8) * 64 + (col >> 1)] = packh2(acc[mt][nt][2], acc[mt][nt][3]);
            }
        }
    }
}

// K1b: v -> v^T fp16 [dk][t] (smem-tiled transpose, half2 stores)
__global__ __launch_bounds__(256) void cvt_vt_kernel()
{
    __shared__ float s_t[128][65];
    const int tb = blockIdx.x * 64;
    const int tid = threadIdx.x;
#pragma unroll
    for (int j = 0; j < 32; j++) {
        int idx = tid + j * 256;
        int t = idx >> 7, dk = idx & 127;
        s_t[dk][t] = g_v[(size_t)(tb + t) * DK + dk];
    }
    __syncthreads();
#pragma unroll
    for (int j = 0; j < 16; j++) {
        int idx = tid + j * 256;
        int dk = idx >> 5, tp = idx & 31;
        reinterpret_cast<uint32_t*>(g_vt)[(size_t)dk * (SEQ / 2) + (tb >> 1) + tp] =
            packh2(s_t[dk][2 * tp], s_t[dk][2 * tp + 1]);
    }
}

// ============================================================
// K2: scores stats ONLY. 1-pass fp16 HMMA, tile 128(s) x 64(t),
// one-shot 48KB, 4 CTAs/SM. Transposed Z epilogue: warp-uniform
// exp-skip per (column, 32-row block) using s_red bounds.
// ============================================================
__global__ __launch_bounds__(256, 4) void scores_kernel()
{
    extern __shared__ uint32_t dsm[];
    const uint32_t sqAddr = smem_u32(dsm);
    const uint32_t skAddr = sqAddr + 32768;
    __shared__ float s_red[4][64];
    __shared__ float s_mcol[64];

    const int t0 = blockIdx.x * 64, s0 = blockIdx.y * 128;
    const int tid = threadIdx.x;
    const int wid = tid >> 5, lane = tid & 31;
    const int g = lane >> 2, tg = lane & 3;
    const int wm = (wid & 3) * 32;
    const int wn = (wid >> 2) * 32;
    const int lr = (lane & 7) + ((lane >> 3) & 1) * 8;
    const int lc = lane >> 4;

    float acc[2][4][4];
#pragma unroll
    for (int i = 0; i < 2; i++)
#pragma unroll
        for (int j = 0; j < 4; j++)
#pragma unroll
            for (int q = 0; q < 4; q++) acc[i][j][q] = 0.f;

#pragma unroll
    for (int j = 0; j < 8; j++) {
        int idx = tid + j * 256, row = idx >> 4, q = idx & 15;
        int blk = q >> 3, qq = q & 7;
        cp16(sqAddr + row * 256 + blk * 128 + ((qq ^ (row & 7)) << 4),
             g_qh + (size_t)(s0 + row) * 64 + q * 4);
    }
#pragma unroll
    for (int j = 0; j < 4; j++) {
        int idx = tid + j * 256, row = idx >> 4, q = idx & 15;
        int blk = q >> 3, qq = q & 7;
        cp16(skAddr + row * 256 + blk * 128 + ((qq ^ (row & 7)) << 4),
             g_kh + (size_t)(t0 + row) * 64 + q * 4);
    }
    CP_COMMIT;
    CP_WAIT0;
    __syncthreads();

#pragma unroll
    for (int j = 0; j < 8; j++) {
        const int ablk = j >> 2, ach = (j & 3) * 2;
        uint32_t Aq[2][4], Bq[2][4];
#pragma unroll
        for (int mt = 0; mt < 2; mt++) {
            const int ra = wm + mt * 16 + lr;
            ldsm_x4(Aq[mt], sqAddr + ra * 256 + ablk * 128 + (((ach + lc) ^ (ra & 7)) << 4));
        }
#pragma unroll
        for (int pr = 0; pr < 2; pr++) {
            const int rb = wn + pr * 16 + lr;
            ldsm_x4(Bq[pr], skAddr + rb * 256 + ablk * 128 + (((ach + lc) ^ (rb & 7)) << 4));
        }
#pragma unroll
        for (int nt = 0; nt < 4; nt++) {
            uint32_t bh[2] = {Bq[nt >> 1][nt & 1], Bq[nt >> 1][2 + (nt & 1)]};
#pragma unroll
            for (int mt = 0; mt < 2; mt++) mma16(acc[mt][nt], Aq[mt], bh);
        }
    }

    __syncthreads();   // all LDSM reads done; alias Q/K region for S dump
    float (*sS)[65] = reinterpret_cast<float(*)[65]>(dsm);   // 128 x 65 fp32 (33.3 KB)

    // per-warp (32-row block) raw column maxes
    float cm[8];
#pragma unroll
    for (int nt = 0; nt < 4; nt++) {
        float a0 = fmaxf(fmaxf(acc[0][nt][0], acc[0][nt][2]), fmaxf(acc[1][nt][0], acc[1][nt][2]));
        float a1 = fmaxf(fmaxf(acc[0][nt][1], acc[0][nt][3]), fmaxf(acc[1][nt][1], acc[1][nt][3]));
        cm[nt * 2] = a0; cm[nt * 2 + 1] = a1;
    }
#pragma unroll
    for (int off = 4; off < 32; off <<= 1)
#pragma unroll
        for (int j = 0; j < 8; j++)
            cm[j] = fmaxf(cm[j], __shfl_xor_sync(0xffffffffu, cm[j], off));
    if (g == 0) {
#pragma unroll
        for (int nt = 0; nt < 4; nt++) {
            s_red[wid & 3][wn + nt * 8 + 2 * tg + 0] = cm[nt * 2 + 0];
            s_red[wid & 3][wn + nt * 8 + 2 * tg + 1] = cm[nt * 2 + 1];
        }
    }
    // dump raw S to smem (row, col)
#pragma unroll
    for (int mt = 0; mt < 2; mt++) {
#pragma unroll
        for (int nt = 0; nt < 4; nt++) {
            const int r0 = wm + mt * 16 + g, r1 = r0 + 8;
            const int col = wn + nt * 8 + 2 * tg;
            sS[r0][col] = acc[mt][nt][0]; sS[r0][col + 1] = acc[mt][nt][1];
            sS[r1][col] = acc[mt][nt][2]; sS[r1][col + 1] = acc[mt][nt][3];
        }
    }
    __syncthreads();
    if (tid < 64) {
        float m4 = fmaxf(fmaxf(s_red[0][tid], s_red[1][tid]), fmaxf(s_red[2][tid], s_red[3][tid]));
        float ms = m4 * SCALE;
        s_mcol[tid] = ms;
        g_pm[(s0 >> 7) * SEQ + t0 + tid] = ms;
    }
    __syncthreads();

    // transposed Z: warp owns 8 whole columns; skip is warp-uniform
    float* zout = &g_pzt[(size_t)(s0 >> 7) * SEQ + t0];
#pragma unroll
    for (int cc = 0; cc < 8; cc++) {
        const int c = wid * 8 + cc;
        const float mS = s_mcol[c];
        float z = 0.f;
#pragma unroll
        for (int p = 0; p < 4; p++) {
            if (s_red[p][c] * SCALE - mS > THRESH) {     // warp-uniform branch
                float d = fmaf(sS[p * 32 + lane][c], SCALE, -mS);
                z += (d > THRESH) ? __expf(d) : 0.f;
            }
        }
#pragma unroll
        for (int off = 16; off; off >>= 1)
            z += __shfl_xor_sync(0xffffffffu, z, off);
        if (lane == 0) zout[c] = z;
    }
}

// ============================================================
// K3: combine tile stats -> global m_t and 1/Z_t
// ============================================================
__global__ void combine_kernel()
{
    const int t = blockIdx.x * 256 + threadIdx.x;
    float m = -3.4e38f;
#pragma unroll 8
    for (int b = 0; b < NT; b++) m = fmaxf(m, g_pm[b * SEQ + t]);
    float Z = 0.f;
#pragma unroll 8
    for (int b = 0; b < NT; b++) {
        float d = g_pm[b * SEQ + t] - m;
        if (d > THRESH - 10.f) Z += g_pzt[b * SEQ + t] * __expf(d);
    }
    g_m[t] = m;
    g_rz[t] = 1.0f / Z;
}

// ============================================================
// K4: FUSED PV (unchanged from R15). grid (SPLIT, SEQ/64).
// ============================================================
__global__ __launch_bounds__(256) void pv_kernel()
{
    extern __shared__ uint32_t dsm[];
    const uint32_t sqA = smem_u32(dsm);
    const uint32_t skA = sqA + 16384;
    const uint32_t svA = sqA + 32768;

    __shared__ float s_m[TCH];
    __shared__ float s_rz[TCH];
    __shared__ float s_adj[TCH];
    __shared__ char  s_flag[TCH / 64];

    const int s0 = blockIdx.y * 64;
    const int bt = blockIdx.y >> 1;
    const int tb = blockIdx.x * TCH;
    const int tid = threadIdx.x;
    const int wid = tid >> 5, lane = tid & 31;
    const int g = lane >> 2, tg = lane & 3;
    const int lr = (lane & 7) + ((lane >> 3) & 1) * 8;
    const int lc = lane >> 4;

#pragma unroll
    for (int j = 0; j < 2; j++) {
        int t = tid + j * 256;
        float m = g_m[tb + t];
        s_m[t] = m;
        s_rz[t] = g_rz[tb + t];
        s_adj[t] = g_pm[(size_t)bt * SEQ + tb + t] - m;
    }
    __syncthreads();
    if (tid < TCH / 64) {
        float mx = -3.4e38f;
#pragma unroll 16
        for (int q = 0; q < 64; q++) mx = fmaxf(mx, s_adj[tid * 64 + q]);
        s_flag[tid] = (mx > THRESH) ? 1 : 0;
    }

#pragma unroll
    for (int j = 0; j < 4; j++) {
        int idx = tid + j * 256, row = idx >> 4, q = idx & 15;
        int blk = q >> 3, qq = q & 7;
        cp16(sqA + row * 256 + blk * 128 + ((qq ^ (row & 7)) << 4),
             g_qh + (size_t)(s0 + row) * 64 + q * 4);
    }
    CP_COMMIT;

    float acc[2][4][4];
#pragma unroll
    for (int i = 0; i < 2; i++)
#pragma unroll
        for (int j = 0; j < 4; j++)
#pragma unroll
            for (int q = 0; q < 4; q++) acc[i][j][q] = 0.f;

    const int wmS = (wid & 1) * 32, wnS = (wid >> 1) * 16;
    const int wdP = (wid >> 1) * 32;

    __syncthreads();

    for (int c = 0; c < TCH / 64; c++) {
        if (!s_flag[c]) continue;
        const int tc = tb + c * 64;
#pragma unroll
        for (int j = 0; j < 4; j++) {
            int idx = tid + j * 256, row = idx >> 4, q = idx & 15;
            int blk = q >> 3, qq = q & 7;
            cp16(skA + row * 256 + blk * 128 + ((qq ^ (row & 7)) << 4),
                 g_kh + (size_t)(tc + row) * 64 + q * 4);
        }
#pragma unroll
        for (int j = 0; j < 4; j++) {
            int idx = tid + j * 256, row = idx >> 3, q = idx & 7;
            cp16(svA + row * 128 + ((q ^ (row & 7)) << 4),
                 g_vt + (size_t)row * SEQ + tc + q * 8);
        }
        CP_COMMIT; CP_WAIT0;
        __syncthreads();

        float sacc[2][2][4];
#pragma unroll
        for (int i = 0; i < 2; i++)
#pragma unroll
            for (int j = 0; j < 2; j++)
#pragma unroll
                for (int q = 0; q < 4; q++) sacc[i][j][q] = 0.f;
#pragma unroll
        for (int j = 0; j < 8; j++) {
            const int ablk = j >> 2, ach = (j & 3) * 2;
            uint32_t Aq[2][4], Bq[4];
#pragma unroll
            for (int mt = 0; mt < 2; mt++) {
                int ra = wmS + mt * 16 + lr;
                ldsm_x4(Aq[mt], sqA + ra * 256 + ablk * 128 + (((ach + lc) ^ (ra & 7)) << 4));
            }
            {
                int rb = wnS + lr;
                ldsm_x4(Bq, skA + rb * 256 + ablk * 128 + (((ach + lc) ^ (rb & 7)) << 4));
            }
#pragma unroll
            for (int nt = 0; nt < 2; nt++) {
                uint32_t bh[2] = {Bq[nt], Bq[2 + nt]};
#pragma unroll
                for (int mt = 0; mt < 2; mt++) mma16(sacc[mt][nt], Aq[mt], bh);
            }
        }
        __syncthreads();

#pragma unroll
        for (int mt = 0; mt < 2; mt++) {
#pragma unroll
            for (int nt = 0; nt < 2; nt++) {
                const int r0 = wmS + mt * 16 + g;
                const int colL = wnS + nt * 8 + 2 * tg;
                const int cg = c * 64 + colL;
                float m0v = s_m[cg], m1v = s_m[cg + 1];
                float z0 = s_rz[cg], z1 = s_rz[cg + 1];
                uint32_t h0 = packh2(__expf(fmaf(sacc[mt][nt][0], SCALE, -m0v)) * z0,
                                     __expf(fmaf(sacc[mt][nt][1], SCALE, -m1v)) * z1);
                uint32_t h1 = packh2(__expf(fmaf(sacc[mt][nt][2], SCALE, -m0v)) * z0,
                                     __expf(fmaf(sacc[mt][nt][3], SCALE, -m1v)) * z1);
                const int bo = colL * 2;
                const int r1 = r0 + 8;
                sts32(skA + r0 * 128 + (((bo >> 4) ^ (r0 & 7)) << 4) + (bo & 15), h0);
                sts32(skA + r1 * 128 + (((bo >> 4) ^ (r1 & 7)) << 4) + (bo & 15), h1);
            }
        }
        __syncthreads();

#pragma unroll
        for (int j = 0; j < 4; j++) {
            uint32_t Ap[2][4], Bv[2][4];
#pragma unroll
            for (int mt = 0; mt < 2; mt++) {
                int ra = wmS + mt * 16 + lr;
                ldsm_x4(Ap[mt], skA + ra * 128 + (((j * 2 + lc) ^ (ra & 7)) << 4));
            }
#pragma unroll
            for (int pr = 0; pr < 2; pr++) {
                int rb = wdP + pr * 16 + lr;
                ldsm_x4(Bv[pr], svA + rb * 128 + (((j * 2 + lc) ^ (rb & 7)) << 4));
            }
#pragma unroll
            for (int nt = 0; nt < 4; nt++) {
                uint32_t bh[2] = {Bv[nt >> 1][nt & 1], Bv[nt >> 1][2 + (nt & 1)]};
#pragma unroll
                for (int mt = 0; mt < 2; mt++) mma16(acc[mt][nt], Ap[mt], bh);
            }
        }
        __syncthreads();
    }

    CP_WAIT0;
    float* po = g_po[blockIdx.x];
#pragma unroll
    for (int mt = 0; mt < 2; mt++) {
#pragma unroll
        for (int nt = 0; nt < 4; nt++) {
            const int r0 = s0 + wmS + mt * 16 + g;
            const int col = wdP + nt * 8 + 2 * tg;
            *reinterpret_cast<float2*>(po + (size_t)r0 * DK + col) =
                make_float2(acc[mt][nt][0], acc[mt][nt][1]);
            *reinterpret_cast<float2*>(po + (size_t)(r0 + 8) * DK + col) =
                make_float2(acc[mt][nt][2], acc[mt][nt][3]);
        }
    }
}

// K5: fixed-order split reduction (float4-wide)
__global__ void pv_reduce_kernel(float* __restrict__ out)
{
    const int i = blockIdx.x * 256 + threadIdx.x;
    float4 s = make_float4(0.f, 0.f, 0.f, 0.f);
#pragma unroll
    for (int p = 0; p < SPLIT; p++) {
        float4 v = reinterpret_cast<const float4*>(g_po[p])[i];
        s.x += v.x; s.y += v.y; s.z += v.z; s.w += v.w;
    }
    reinterpret_cast<float4*>(out)[i] = s;
}

// ============================================================
extern "C" void kernel_launch(void* const* d_in, const int* in_sizes, int n_in,
                              void* d_out, int out_size)
{
    const float* x  = (const float*)d_in[0];
    const float* wq = (const float*)d_in[1];
    const float* wk = (const float*)d_in[2];
    const float* wv = (const float*)d_in[3];
    float* out = (float*)d_out;

    cudaFuncSetAttribute(qkv_kernel, cudaFuncAttributeMaxDynamicSharedMemorySize, 49152);
    cudaFuncSetAttribute(scores_kernel, cudaFuncAttributeMaxDynamicSharedMemorySize, 49152);
    cudaFuncSetAttribute(pv_kernel, cudaFuncAttributeMaxDynamicSharedMemorySize, 49152);

    cvt_x_kernel<<<SEQ * CTX / 4 / 256, 256>>>(x);
    cvt_w_kernel<<<3 * DK * 512 / 256, 256>>>(wq, wk, wv);
    qkv_kernel<<<dim3(SEQ / 64, 3), 256, 49152>>>();
    cvt_vt_kernel<<<SEQ / 64, 256>>>();
    scores_kernel<<<dim3(SEQ / 64, SEQ / 128), 256, 49152>>>();
    combine_kernel<<<SEQ / 256, 256>>>();
    pv_kernel<<<dim3(SPLIT, SEQ / 64), 256, 49152>>>();
    pv_reduce_kernel<<<SEQ * DK / 4 / 256, 256>>>(out);
}

// round 17
// speedup vs baseline: 1.1615x; 1.1615x over previous
#include <cuda_runtime.h>
#include <cuda_fp16.h>
#include <cstdint>

#define SEQ 8192
#define CTX 2048
#define DK  128
#define NT2 128                   // SEQ/64 stats tiles (64-row granularity)
#define SPLIT 16
#define TCH (SEQ / SPLIT)         // 512 t-columns per pv block
#define SCALE 11.313708498984760f
#define THRESH -25.0f

// ---- scratch (device globals) ----
__device__ uint32_t g_xh[(size_t)SEQ * (CTX / 2)];         // 32 MB fp16 x
__device__ uint32_t g_wh[3 * DK * (CTX / 2)];              // 3 MB   [mat][n][k]
__device__ uint32_t g_qh[(size_t)SEQ * (DK / 2)];          // 2 MB fp16 q
__device__ uint32_t g_kh[(size_t)SEQ * (DK / 2)];          // 2 MB fp16 k
__device__ float  g_v[SEQ * DK];                           // 4 MB fp32 v
__device__ __half g_vt[(size_t)DK * SEQ];                  // 2 MB fp16 v^T [dk][t]
__device__ float  g_pm[NT2 * SEQ];                         // per-64-row-tile col max (scaled)
__device__ float  g_pzt[NT2 * SEQ];                        // per-64-row-tile Z partial
__device__ float  g_m[SEQ];
__device__ float  g_rz[SEQ];
__device__ float  g_po[SPLIT][SEQ * DK];                   // 64 MB pv partials

// ============================================================
// helpers
// ============================================================
__device__ __forceinline__ uint32_t smem_u32(const void* p) {
    uint32_t a;
    asm("{ .reg .u64 t; cvta.to.shared.u64 t, %1; cvt.u32.u64 %0, t; }" : "=r"(a) : "l"(p));
    return a;
}
__device__ __forceinline__ void cp16(uint32_t dst, const void* src) {
    asm volatile("cp.async.cg.shared.global [%0], [%1], 16;" :: "r"(dst), "l"(src));
}
#define CP_COMMIT asm volatile("cp.async.commit_group;" ::: "memory")
#define CP_WAIT0  asm volatile("cp.async.wait_group 0;" ::: "memory")

__device__ __forceinline__ uint32_t packh2(float x0, float x1) {
    uint32_t h;
    asm("cvt.rn.f16x2.f32 %0, %1, %2;" : "=r"(h) : "f"(x1), "f"(x0));
    return h;
}
__device__ __forceinline__ void mma16(float* c, const uint32_t* a, const uint32_t* b) {
    asm("mma.sync.aligned.m16n8k16.row.col.f32.f16.f16.f32 "
        "{%0,%1,%2,%3}, {%4,%5,%6,%7}, {%8,%9}, {%0,%1,%2,%3};"
        : "+f"(c[0]), "+f"(c[1]), "+f"(c[2]), "+f"(c[3])
        : "r"(a[0]), "r"(a[1]), "r"(a[2]), "r"(a[3]), "r"(b[0]), "r"(b[1]));
}
__device__ __forceinline__ void ldsm_x4(uint32_t* d, uint32_t a) {
    asm volatile("ldmatrix.sync.aligned.m8n8.x4.shared.b16 {%0,%1,%2,%3}, [%4];"
                 : "=r"(d[0]), "=r"(d[1]), "=r"(d[2]), "=r"(d[3]) : "r"(a));
}
__device__ __forceinline__ void sts32(uint32_t addr, uint32_t v) {
    asm volatile("st.shared.b32 [%0], %1;" :: "r"(addr), "r"(v) : "memory");
}

// ============================================================
// K0a: x -> row-major fp16
// ============================================================
__global__ __launch_bounds__(256) void cvt_x_kernel(const float* __restrict__ x)
{
    const int i = blockIdx.x * 256 + threadIdx.x;
    float4 v = reinterpret_cast<const float4*>(x)[i];
    g_xh[2 * (size_t)i]     = packh2(v.x, v.y);
    g_xh[2 * (size_t)i + 1] = packh2(v.z, v.w);
}

// K0b: w^T -> fp16, [mat][n][k]
__global__ __launch_bounds__(256) void cvt_w_kernel(
    const float* __restrict__ wq, const float* __restrict__ wk, const float* __restrict__ wv)
{
    const int i = blockIdx.x * 256 + threadIdx.x;
    const int mat = i / (DK * 512);
    const int r = i % (DK * 512);
    const int n = r >> 9;
    const int k4 = (r & 511) * 4;
    const float* w = (mat == 0) ? wq : (mat == 1) ? wk : wv;
    float w0 = w[(size_t)(k4 + 0) * DK + n];
    float w1 = w[(size_t)(k4 + 1) * DK + n];
    float w2 = w[(size_t)(k4 + 2) * DK + n];
    float w3 = w[(size_t)(k4 + 3) * DK + n];
    uint32_t* base = g_wh + ((size_t)(mat * DK + n)) * 1024 + (k4 >> 1);
    base[0] = packh2(w0, w1);
    base[1] = packh2(w2, w3);
}

// ============================================================
// K1: Q/K/V = x @ w, 1-pass fp16. Tile 64m x 128n, BK=64, 48KB 2-buf, 4 CTAs/SM.
// ============================================================
__global__ __launch_bounds__(256, 4) void qkv_kernel()
{
    extern __shared__ uint32_t dsm[];
    const uint32_t base0 = smem_u32(dsm);

    const int m0 = blockIdx.x * 64;
    const int mat = blockIdx.y;
    const int tid = threadIdx.x;
    const int wid = tid >> 5, lane = tid & 31;
    const int g = lane >> 2, tg = lane & 3;
    const int wm = (wid & 1) * 32;
    const int wn = (wid >> 1) * 32;
    const int lr = (lane & 7) + ((lane >> 3) & 1) * 8;
    const int lc = lane >> 4;

    float acc[2][4][4];
#pragma unroll
    for (int i = 0; i < 2; i++)
#pragma unroll
        for (int j = 0; j < 4; j++)
#pragma unroll
            for (int q = 0; q < 4; q++) acc[i][j][q] = 0.f;

#define QKV_ISSUE(kc, buf)                                                        \
    do {                                                                          \
        _Pragma("unroll")                                                         \
        for (int j = 0; j < 2; j++) {                                             \
            int idx = tid + j * 256, row = idx >> 3, q = idx & 7;                 \
            cp16(base0 + (buf) * 8192 + row * 128 + ((q ^ (row & 7)) << 4),       \
                 g_xh + (size_t)(m0 + row) * (CTX / 2) + (kc) * 32 + q * 4);      \
        }                                                                         \
        _Pragma("unroll")                                                         \
        for (int j = 0; j < 4; j++) {                                             \
            int idx = tid + j * 256, row = idx >> 3, q = idx & 7;                 \
            cp16(base0 + 16384 + (buf) * 16384 + row * 128 + ((q ^ (row & 7)) << 4), \
                 g_wh + (size_t)(mat * DK + row) * 1024 + (kc) * 32 + q * 4);     \
        }                                                                         \
    } while (0)

    QKV_ISSUE(0, 0);
    CP_COMMIT;
    const int NC = CTX / 64;
    for (int kc = 0; kc < NC; kc++) {
        CP_WAIT0;
        __syncthreads();
        if (kc + 1 < NC) { QKV_ISSUE(kc + 1, (kc + 1) & 1); CP_COMMIT; }
        const int buf = kc & 1;
        const uint32_t aB = base0 + buf * 8192u;
        const uint32_t bB = base0 + 16384u + buf * 16384u;
#pragma unroll
        for (int j = 0; j < 4; j++) {
            uint32_t Aq[2][4], Bq[2][4];
#pragma unroll
            for (int mt = 0; mt < 2; mt++) {
                const int ra = wm + mt * 16 + lr;
                ldsm_x4(Aq[mt], aB + ra * 128 + (((j * 2 + lc) ^ (ra & 7)) << 4));
            }
#pragma unroll
            for (int pr = 0; pr < 2; pr++) {
                const int rb = wn + pr * 16 + lr;
                ldsm_x4(Bq[pr], bB + rb * 128 + (((j * 2 + lc) ^ (rb & 7)) << 4));
            }
#pragma unroll
            for (int nt = 0; nt < 4; nt++) {
                uint32_t bh[2] = {Bq[nt >> 1][nt & 1], Bq[nt >> 1][2 + (nt & 1)]};
#pragma unroll
                for (int mt = 0; mt < 2; mt++) mma16(acc[mt][nt], Aq[mt], bh);
            }
        }
    }
#undef QKV_ISSUE

#pragma unroll
    for (int mt = 0; mt < 2; mt++) {
#pragma unroll
        for (int nt = 0; nt < 4; nt++) {
            const int r0 = m0 + wm + mt * 16 + g;
            const int col = wn + nt * 8 + 2 * tg;
            if (mat == 2) {
                *reinterpret_cast<float2*>(g_v + (size_t)r0 * DK + col) =
                    make_float2(acc[mt][nt][0], acc[mt][nt][1]);
                *reinterpret_cast<float2*>(g_v + (size_t)(r0 + 8) * DK + col) =
                    make_float2(acc[mt][nt][2], acc[mt][nt][3]);
            } else {
                uint32_t* dst = (mat == 0) ? g_qh : g_kh;
                dst[(size_t)r0 * 64 + (col >> 1)] = packh2(acc[mt][nt][0], acc[mt][nt][1]);
                dst[(size_t)(r0 + 8) * 64 + (col >> 1)] = packh2(acc[mt][nt][2], acc[mt][nt][3]);
            }
        }
    }
}

// K1b: v -> v^T fp16 [dk][t] (smem-tiled transpose, half2 stores)
__global__ __launch_bounds__(256) void cvt_vt_kernel()
{
    __shared__ float s_t[128][65];
    const int tb = blockIdx.x * 64;
    const int tid = threadIdx.x;
#pragma unroll
    for (int j = 0; j < 32; j++) {
        int idx = tid + j * 256;
        int t = idx >> 7, dk = idx & 127;
        s_t[dk][t] = g_v[(size_t)(tb + t) * DK + dk];
    }
    __syncthreads();
#pragma unroll
    for (int j = 0; j < 16; j++) {
        int idx = tid + j * 256;
        int dk = idx >> 5, tp = idx & 31;
        reinterpret_cast<uint32_t*>(g_vt)[(size_t)dk * (SEQ / 2) + (tb >> 1) + tp] =
            packh2(s_t[dk][2 * tp], s_t[dk][2 * tp + 1]);
    }
}

// ============================================================
// K2: scores stats ONLY (R15 epilogue, 64-row granularity stats).
// 1-pass fp16 HMMA, tile 128(s) x 64(t), one-shot 48KB, 4 CTAs/SM.
// Outputs per 64-row half: g_pm (scaled max), g_pzt (Z partial).
// ============================================================
__global__ __launch_bounds__(256, 4) void scores_kernel()
{
    extern __shared__ uint32_t dsm[];
    const uint32_t sqAddr = smem_u32(dsm);
    const uint32_t skAddr = sqAddr + 32768;
    __shared__ float s_m64[2][64];

    const int t0 = blockIdx.x * 64, s0 = blockIdx.y * 128;
    const int tid = threadIdx.x;
    const int wid = tid >> 5, lane = tid & 31;
    const int g = lane >> 2, tg = lane & 3;
    const int wm = (wid & 3) * 32;
    const int wn = (wid >> 2) * 32;
    const int lr = (lane & 7) + ((lane >> 3) & 1) * 8;
    const int lc = lane >> 4;

    float acc[2][4][4];
#pragma unroll
    for (int i = 0; i < 2; i++)
#pragma unroll
        for (int j = 0; j < 4; j++)
#pragma unroll
            for (int q = 0; q < 4; q++) acc[i][j][q] = 0.f;

#pragma unroll
    for (int j = 0; j < 8; j++) {
        int idx = tid + j * 256, row = idx >> 4, q = idx & 15;
        int blk = q >> 3, qq = q & 7;
        cp16(sqAddr + row * 256 + blk * 128 + ((qq ^ (row & 7)) << 4),
             g_qh + (size_t)(s0 + row) * 64 + q * 4);
    }
#pragma unroll
    for (int j = 0; j < 4; j++) {
        int idx = tid + j * 256, row = idx >> 4, q = idx & 15;
        int blk = q >> 3, qq = q & 7;
        cp16(skAddr + row * 256 + blk * 128 + ((qq ^ (row & 7)) << 4),
             g_kh + (size_t)(t0 + row) * 64 + q * 4);
    }
    CP_COMMIT;
    CP_WAIT0;
    __syncthreads();

#pragma unroll
    for (int j = 0; j < 8; j++) {
        const int ablk = j >> 2, ach = (j & 3) * 2;
        uint32_t Aq[2][4], Bq[2][4];
#pragma unroll
        for (int mt = 0; mt < 2; mt++) {
            const int ra = wm + mt * 16 + lr;
            ldsm_x4(Aq[mt], sqAddr + ra * 256 + ablk * 128 + (((ach + lc) ^ (ra & 7)) << 4));
        }
#pragma unroll
        for (int pr = 0; pr < 2; pr++) {
            const int rb = wn + pr * 16 + lr;
            ldsm_x4(Bq[pr], skAddr + rb * 256 + ablk * 128 + (((ach + lc) ^ (rb & 7)) << 4));
        }
#pragma unroll
        for (int nt = 0; nt < 4; nt++) {
            uint32_t bh[2] = {Bq[nt >> 1][nt & 1], Bq[nt >> 1][2 + (nt & 1)]};
#pragma unroll
            for (int mt = 0; mt < 2; mt++) mma16(acc[mt][nt], Aq[mt], bh);
        }
    }

    __syncthreads();   // all LDSM reads done; alias K region for reductions
    float (*s_red)[64] = reinterpret_cast<float(*)[64]>(dsm + 8192);

    // per-warp (32-row block) raw column maxes
    float cm[8];
#pragma unroll
    for (int nt = 0; nt < 4; nt++) {
        float a0 = fmaxf(fmaxf(acc[0][nt][0], acc[0][nt][2]), fmaxf(acc[1][nt][0], acc[1][nt][2]));
        float a1 = fmaxf(fmaxf(acc[0][nt][1], acc[0][nt][3]), fmaxf(acc[1][nt][1], acc[1][nt][3]));
        cm[nt * 2] = a0; cm[nt * 2 + 1] = a1;
    }
#pragma unroll
    for (int off = 4; off < 32; off <<= 1)
#pragma unroll
        for (int j = 0; j < 8; j++)
            cm[j] = fmaxf(cm[j], __shfl_xor_sync(0xffffffffu, cm[j], off));
    if (g == 0) {
#pragma unroll
        for (int nt = 0; nt < 4; nt++) {
            s_red[wid & 3][wn + nt * 8 + 2 * tg + 0] = cm[nt * 2 + 0];
            s_red[wid & 3][wn + nt * 8 + 2 * tg + 1] = cm[nt * 2 + 1];
        }
    }
    __syncthreads();
    if (tid < 64) {
        float h0 = fmaxf(s_red[0][tid], s_red[1][tid]) * SCALE;
        float h1 = fmaxf(s_red[2][tid], s_red[3][tid]) * SCALE;
        s_m64[0][tid] = h0;
        s_m64[1][tid] = h1;
        const int bt2 = 2 * (s0 >> 7);
        g_pm[(size_t)bt2 * SEQ + t0 + tid] = h0;
        g_pm[(size_t)(bt2 + 1) * SEQ + t0 + tid] = h1;
    }
    __syncthreads();

    // half index of this warp's rows (rows wm..wm+31; half = wm/64)
    const int half = (wid & 3) >> 1;
    float mcolS[8];
#pragma unroll
    for (int nt = 0; nt < 4; nt++) {
        const int c = wn + nt * 8 + 2 * tg;
        mcolS[nt * 2 + 0] = s_m64[half][c];
        mcolS[nt * 2 + 1] = s_m64[half][c + 1];
    }

    float z[8];
#pragma unroll
    for (int j = 0; j < 8; j++) z[j] = 0.f;
#pragma unroll
    for (int mt = 0; mt < 2; mt++) {
#pragma unroll
        for (int nt = 0; nt < 4; nt++) {
            float d00 = fmaf(acc[mt][nt][0], SCALE, -mcolS[nt * 2]);
            float d01 = fmaf(acc[mt][nt][1], SCALE, -mcolS[nt * 2 + 1]);
            float d10 = fmaf(acc[mt][nt][2], SCALE, -mcolS[nt * 2]);
            float d11 = fmaf(acc[mt][nt][3], SCALE, -mcolS[nt * 2 + 1]);
            z[nt * 2 + 0] += (d00 > THRESH ? __expf(d00) : 0.f) + (d10 > THRESH ? __expf(d10) : 0.f);
            z[nt * 2 + 1] += (d01 > THRESH ? __expf(d01) : 0.f) + (d11 > THRESH ? __expf(d11) : 0.f);
        }
    }
#pragma unroll
    for (int off = 4; off < 32; off <<= 1)
#pragma unroll
        for (int j = 0; j < 8; j++)
            z[j] += __shfl_xor_sync(0xffffffffu, z[j], off);
    __syncthreads();
    if (g == 0) {
#pragma unroll
        for (int nt = 0; nt < 4; nt++) {
            s_red[wid & 3][wn + nt * 8 + 2 * tg + 0] = z[nt * 2 + 0];
            s_red[wid & 3][wn + nt * 8 + 2 * tg + 1] = z[nt * 2 + 1];
        }
    }
    __syncthreads();
    if (tid < 64) {
        const int bt2 = 2 * (s0 >> 7);
        g_pzt[(size_t)bt2 * SEQ + t0 + tid] = s_red[0][tid] + s_red[1][tid];
        g_pzt[(size_t)(bt2 + 1) * SEQ + t0 + tid] = s_red[2][tid] + s_red[3][tid];
    }
}

// ============================================================
// K3: combine 64-row tile stats -> global m_t and 1/Z_t
// ============================================================
__global__ void combine_kernel()
{
    const int t = blockIdx.x * 256 + threadIdx.x;
    float m = -3.4e38f;
#pragma unroll 8
    for (int b = 0; b < NT2; b++) m = fmaxf(m, g_pm[b * SEQ + t]);
    float Z = 0.f;
#pragma unroll 8
    for (int b = 0; b < NT2; b++) {
        float d = g_pm[b * SEQ + t] - m;
        if (d > THRESH - 10.f) Z += g_pzt[b * SEQ + t] * __expf(d);
    }
    g_m[t] = m;
    g_rz[t] = 1.0f / Z;
}

// ============================================================
// K4: FUSED PV (R15). grid (SPLIT, SEQ/64). 64-row stats tiles
// now exactly match pv blocks -> tighter liveness bound.
// ============================================================
__global__ __launch_bounds__(256) void pv_kernel()
{
    extern __shared__ uint32_t dsm[];
    const uint32_t sqA = smem_u32(dsm);
    const uint32_t skA = sqA + 16384;
    const uint32_t svA = sqA + 32768;

    __shared__ float s_m[TCH];
    __shared__ float s_rz[TCH];
    __shared__ float s_adj[TCH];
    __shared__ char  s_flag[TCH / 64];

    const int s0 = blockIdx.y * 64;
    const int bt = blockIdx.y;           // 64-row stats tile index (exact match)
    const int tb = blockIdx.x * TCH;
    const int tid = threadIdx.x;
    const int wid = tid >> 5, lane = tid & 31;
    const int g = lane >> 2, tg = lane & 3;
    const int lr = (lane & 7) + ((lane >> 3) & 1) * 8;
    const int lc = lane >> 4;

#pragma unroll
    for (int j = 0; j < 2; j++) {
        int t = tid + j * 256;
        float m = g_m[tb + t];
        s_m[t] = m;
        s_rz[t] = g_rz[tb + t];
        s_adj[t] = g_pm[(size_t)bt * SEQ + tb + t] - m;
    }
    __syncthreads();
    if (tid < TCH / 64) {
        float mx = -3.4e38f;
#pragma unroll 16
        for (int q = 0; q < 64; q++) mx = fmaxf(mx, s_adj[tid * 64 + q]);
        s_flag[tid] = (mx > THRESH) ? 1 : 0;
    }

#pragma unroll
    for (int j = 0; j < 4; j++) {
        int idx = tid + j * 256, row = idx >> 4, q = idx & 15;
        int blk = q >> 3, qq = q & 7;
        cp16(sqA + row * 256 + blk * 128 + ((qq ^ (row & 7)) << 4),
             g_qh + (size_t)(s0 + row) * 64 + q * 4);
    }
    CP_COMMIT;

    float acc[2][4][4];
#pragma unroll
    for (int i = 0; i < 2; i++)
#pragma unroll
        for (int j = 0; j < 4; j++)
#pragma unroll
            for (int q = 0; q < 4; q++) acc[i][j][q] = 0.f;

    const int wmS = (wid & 1) * 32, wnS = (wid >> 1) * 16;
    const int wdP = (wid >> 1) * 32;

    __syncthreads();

    for (int c = 0; c < TCH / 64; c++) {
        if (!s_flag[c]) continue;
        const int tc = tb + c * 64;
#pragma unroll
        for (int j = 0; j < 4; j++) {
            int idx = tid + j * 256, row = idx >> 4, q = idx & 15;
            int blk = q >> 3, qq = q & 7;
            cp16(skA + row * 256 + blk * 128 + ((qq ^ (row & 7)) << 4),
                 g_kh + (size_t)(tc + row) * 64 + q * 4);
        }
#pragma unroll
        for (int j = 0; j < 4; j++) {
            int idx = tid + j * 256, row = idx >> 3, q = idx & 7;
            cp16(svA + row * 128 + ((q ^ (row & 7)) << 4),
                 g_vt + (size_t)row * SEQ + tc + q * 8);
        }
        CP_COMMIT; CP_WAIT0;
        __syncthreads();

        float sacc[2][2][4];
#pragma unroll
        for (int i = 0; i < 2; i++)
#pragma unroll
            for (int j = 0; j < 2; j++)
#pragma unroll
                for (int q = 0; q < 4; q++) sacc[i][j][q] = 0.f;
#pragma unroll
        for (int j = 0; j < 8; j++) {
            const int ablk = j >> 2, ach = (j & 3) * 2;
            uint32_t Aq[2][4], Bq[4];
#pragma unroll
            for (int mt = 0; mt < 2; mt++) {
                int ra = wmS + mt * 16 + lr;
                ldsm_x4(Aq[mt], sqA + ra * 256 + ablk * 128 + (((ach + lc) ^ (ra & 7)) << 4));
            }
            {
                int rb = wnS + lr;
                ldsm_x4(Bq, skA + rb * 256 + ablk * 128 + (((ach + lc) ^ (rb & 7)) << 4));
            }
#pragma unroll
            for (int nt = 0; nt < 2; nt++) {
                uint32_t bh[2] = {Bq[nt], Bq[2 + nt]};
#pragma unroll
                for (int mt = 0; mt < 2; mt++) mma16(sacc[mt][nt], Aq[mt], bh);
            }
        }
        __syncthreads();

#pragma unroll
        for (int mt = 0; mt < 2; mt++) {
#pragma unroll
            for (int nt = 0; nt < 2; nt++) {
                const int r0 = wmS + mt * 16 + g;
                const int colL = wnS + nt * 8 + 2 * tg;
                const int cg = c * 64 + colL;
                float m0v = s_m[cg], m1v = s_m[cg + 1];
                float z0 = s_rz[cg], z1 = s_rz[cg + 1];
                uint32_t h0 = packh2(__expf(fmaf(sacc[mt][nt][0], SCALE, -m0v)) * z0,
                                     __expf(fmaf(sacc[mt][nt][1], SCALE, -m1v)) * z1);
                uint32_t h1 = packh2(__expf(fmaf(sacc[mt][nt][2], SCALE, -m0v)) * z0,
                                     __expf(fmaf(sacc[mt][nt][3], SCALE, -m1v)) * z1);
                const int bo = colL * 2;
                const int r1 = r0 + 8;
                sts32(skA + r0 * 128 + (((bo >> 4) ^ (r0 & 7)) << 4) + (bo & 15), h0);
                sts32(skA + r1 * 128 + (((bo >> 4) ^ (r1 & 7)) << 4) + (bo & 15), h1);
            }
        }
        __syncthreads();

#pragma unroll
        for (int j = 0; j < 4; j++) {
            uint32_t Ap[2][4], Bv[2][4];
#pragma unroll
            for (int mt = 0; mt < 2; mt++) {
                int ra = wmS + mt * 16 + lr;
                ldsm_x4(Ap[mt], skA + ra * 128 + (((j * 2 + lc) ^ (ra & 7)) << 4));
            }
#pragma unroll
            for (int pr = 0; pr < 2; pr++) {
                int rb = wdP + pr * 16 + lr;
                ldsm_x4(Bv[pr], svA + rb * 128 + (((j * 2 + lc) ^ (rb & 7)) << 4));
            }
#pragma unroll
            for (int nt = 0; nt < 4; nt++) {
                uint32_t bh[2] = {Bv[nt >> 1][nt & 1], Bv[nt >> 1][2 + (nt & 1)]};
#pragma unroll
                for (int mt = 0; mt < 2; mt++) mma16(acc[mt][nt], Ap[mt], bh);
            }
        }
        __syncthreads();
    }

    CP_WAIT0;
    float* po = g_po[blockIdx.x];
#pragma unroll
    for (int mt = 0; mt < 2; mt++) {
#pragma unroll
        for (int nt = 0; nt < 4; nt++) {
            const int r0 = s0 + wmS + mt * 16 + g;
            const int col = wdP + nt * 8 + 2 * tg;
            *reinterpret_cast<float2*>(po + (size_t)r0 * DK + col) =
                make_float2(acc[mt][nt][0], acc[mt][nt][1]);
            *reinterpret_cast<float2*>(po + (size_t)(r0 + 8) * DK + col) =
                make_float2(acc[mt][nt][2], acc[mt][nt][3]);
        }
    }
}

// K5: fixed-order split reduction (float4-wide)
__global__ void pv_reduce_kernel(float* __restrict__ out)
{
    const int i = blockIdx.x * 256 + threadIdx.x;
    float4 s = make_float4(0.f, 0.f, 0.f, 0.f);
#pragma unroll
    for (int p = 0; p < SPLIT; p++) {
        float4 v = reinterpret_cast<const float4*>(g_po[p])[i];
        s.x += v.x; s.y += v.y; s.z += v.z; s.w += v.w;
    }
    reinterpret_cast<float4*>(out)[i] = s;
}

// ============================================================
extern "C" void kernel_launch(void* const* d_in, const int* in_sizes, int n_in,
                              void* d_out, int out_size)
{
    const float* x  = (const float*)d_in[0];
    const float* wq = (const float*)d_in[1];
    const float* wk = (const float*)d_in[2];
    const float* wv = (const float*)d_in[3];
    float* out = (float*)d_out;

    cudaFuncSetAttribute(qkv_kernel, cudaFuncAttributeMaxDynamicSharedMemorySize, 49152);
    cudaFuncSetAttribute(scores_kernel, cudaFuncAttributeMaxDynamicSharedMemorySize, 49152);
    cudaFuncSetAttribute(pv_kernel, cudaFuncAttributeMaxDynamicSharedMemorySize, 49152);

    cvt_x_kernel<<<SEQ * CTX / 4 / 256, 256>>>(x);
    cvt_w_kernel<<<3 * DK * 512 / 256, 256>>>(wq, wk, wv);
    qkv_kernel<<<dim3(SEQ / 64, 3), 256, 49152>>>();
    cvt_vt_kernel<<<SEQ / 64, 256>>>();
    scores_kernel<<<dim3(SEQ / 64, SEQ / 128), 256, 49152>>>();
    combine_kernel<<<SEQ / 256, 256>>>();
    pv_kernel<<<dim3(SPLIT, SEQ / 64), 256, 49152>>>();
    pv_reduce_kernel<<<SEQ * DK / 4 / 256, 256>>>(out);
}